// round 15
// baseline (speedup 1.0000x reference)
#include <cuda_runtime.h>
#include <cuda_bf16.h>
#include <cstdint>

#define Nn 4
#define Mm 1024
#define Dd 64
#define Ll 16
#define Bb 4096
#define BL 65536
#define DECAYF 0.999f
#define EPSF 1e-5f
#define COMMITF 0.05f

#define OFF_ZQ   0LL
#define OFF_LOSS 16777216LL
#define OFF_PERP 16777217LL
#define OFF_IDX  16777218LL
#define OFF_EZQ  17039362LL
#define OFF_EMB  33816578LL
#define OFF_CNT  34078722LL
#define OFF_EMW  34082818LL

__device__ float    g_xt[Nn * BL * Dd];
__device__ uint32_t g_xbf[Nn * BL * 32];    // x bf16 pairs, 128B/row
__device__ uint32_t g_ebf[Nn * Mm * 32];    // emb bf16 pairs, 128B/row
__device__ float    g_xnorm[Nn * BL];
__device__ int      g_idx[Nn * BL];
__device__ float    g_dw[Nn * Mm * Dd];
__device__ int      g_cnt[Nn * Mm];
__device__ float    g_enorm[Nn * Mm];
__device__ int      g_emaxbits[Nn];
__device__ float    g_fcnt[Nn * Mm];
__device__ float    g_losspart[Bb * Nn];
__device__ unsigned long long g_key[Nn * BL];   // per-row argmin key
__device__ uint32_t g_cand[2097152];            // candidate list
__device__ int      g_nc;

#define SWZ(off) ((off) ^ (((off) >> 3) & 0x70))
#define CP_ASYNC16(dst, src) \
    asm volatile("cp.async.cg.shared.global [%0], [%1], 16;" :: "r"(dst), "l"(src))
#define CP_COMMIT() asm volatile("cp.async.commit_group;" ::: "memory")
#define CP_WAIT(nconst) asm volatile("cp.async.wait_group %0;" :: "n"(nconst) : "memory")
#define LDSM4(r0, r1, r2, r3, addr) \
    asm volatile("ldmatrix.sync.aligned.m8n8.x4.shared.b16 {%0,%1,%2,%3}, [%4];" \
                 : "=r"(r0), "=r"(r1), "=r"(r2), "=r"(r3) : "r"(addr))

__device__ __forceinline__ uint32_t smem_u32(const void* p) {
    uint32_t a;
    asm("{ .reg .u64 t; cvta.to.shared.u64 t, %1; cvt.u32.u64 %0, t; }" : "=r"(a) : "l"(p));
    return a;
}
__device__ __forceinline__ void mma16816(float* d, const uint32_t* a, const uint32_t* b) {
    asm volatile("mma.sync.aligned.m16n8k16.row.col.f32.bf16.bf16.f32 "
                 "{%0,%1,%2,%3}, {%4,%5,%6,%7}, {%8,%9}, {%0,%1,%2,%3};"
                 : "+f"(d[0]), "+f"(d[1]), "+f"(d[2]), "+f"(d[3])
                 : "r"(a[0]), "r"(a[1]), "r"(a[2]), "r"(a[3]), "r"(b[0]), "r"(b[1]));
}
__device__ __forceinline__ void do_mma(float* acc, const uint32_t (&af)[4][4],
                                       const uint32_t* bf) {
    acc[0] = 0.f; acc[1] = 0.f; acc[2] = 0.f; acc[3] = 0.f;
    mma16816(acc, af[0], bf + 0);
    mma16816(acc, af[1], bf + 2);
    mma16816(acc, af[2], bf + 4);
    mma16816(acc, af[3], bf + 6);
}

// ---------------------------------------------------------------------------
__global__ void k_zero() {
    int i = blockIdx.x * 256 + threadIdx.x;          // 262144 threads
    if (i < Nn * Mm * Dd) g_dw[i] = 0.0f;
    if (i < Nn * Mm)      g_cnt[i] = 0;
    if (i < Nn)           g_emaxbits[i] = 0;
    g_key[i] = 0xFFFFFFFFFFFFFFFFULL;
    if (i == 0) g_nc = 0;
}

// ---------------------------------------------------------------------------
__global__ void k_transpose(const float* __restrict__ x) {
    __shared__ float s[16][65];
    int bn = blockIdx.x;
    int b = bn >> 2, n = bn & 3;
    int t = threadIdx.x;
    const float4* xp = (const float4*)(x + (long long)b * 4096 + n * 1024);
    float4 v = xp[t];
    int d = t >> 2, lb = (t & 3) * 4;
    s[lb + 0][d] = v.x; s[lb + 1][d] = v.y; s[lb + 2][d] = v.z; s[lb + 3][d] = v.w;
    __syncthreads();
    int r = t >> 4, c = t & 15;
    float4 w = make_float4(s[r][c * 4], s[r][c * 4 + 1], s[r][c * 4 + 2], s[r][c * 4 + 3]);
    size_t row = (size_t)n * BL + b * 16 + r;
    ((float4*)g_xt)[row * 16 + c] = w;
    g_xbf[row * 32 + c * 2] =
        (uint32_t)__bfloat16_as_ushort(__float2bfloat16_rn(w.x)) |
        ((uint32_t)__bfloat16_as_ushort(__float2bfloat16_rn(w.y)) << 16);
    g_xbf[row * 32 + c * 2 + 1] =
        (uint32_t)__bfloat16_as_ushort(__float2bfloat16_rn(w.z)) |
        ((uint32_t)__bfloat16_as_ushort(__float2bfloat16_rn(w.w)) << 16);
    if (t < 16) {
        float acc = 0.0f;
        #pragma unroll 8
        for (int dd = 0; dd < 64; dd++) {
            float vv = s[t][dd];
            acc = __fadd_rn(acc, __fmul_rn(vv, vv));
        }
        g_xnorm[(size_t)n * BL + b * 16 + t] = acc;
    }
}

// ---------------------------------------------------------------------------
__global__ void k_enorm(const float* __restrict__ emb) {
    int i = blockIdx.x * blockDim.x + threadIdx.x;   // 0..4095
    const float* e = emb + (size_t)i * 64;
    float s = 0.0f;
    #pragma unroll 8
    for (int d2 = 0; d2 < 32; d2++) {
        float v0 = e[2 * d2], v1 = e[2 * d2 + 1];
        s = __fadd_rn(s, __fmul_rn(v0, v0));
        s = __fadd_rn(s, __fmul_rn(v1, v1));
        g_ebf[(size_t)i * 32 + d2] =
            (uint32_t)__bfloat16_as_ushort(__float2bfloat16_rn(v0)) |
            ((uint32_t)__bfloat16_as_ushort(__float2bfloat16_rn(v1)) << 16);
    }
    g_enorm[i] = s;
    atomicMax(&g_emaxbits[i >> 10], __float_as_int(s));
}

// ---------------------------------------------------------------------------
// Two-pass HMMA prune, software-pipelined B fragments.
#define SMO_ENS  0               // 4096B
#define SMO_XN   4096            // 512B
#define SMO_A    4608            // 16384B -> 20992
#define SMO_B    20992           // 2 x 16384 -> 53760
#define SMO_LIST 53760           // 1024 u32 -> 57856
#define SMO_CNT  57856
#define SMO_BASE 57860
#define SM_BYTES 57984
#define LCAP 1024

extern __shared__ char smx[];
__global__ void __launch_bounds__(256, 3)
k_argmin(float* __restrict__ out) {
    const int n = blockIdx.y;
    const int kbase = blockIdx.x * 128;
    const int t = threadIdx.x;
    const int lane = t & 31, w = t >> 5;
    const int g = lane >> 2, q = lane & 3;
    float* ens = (float*)(smx + SMO_ENS);
    float* xn  = (float*)(smx + SMO_XN);
    uint32_t* slist = (uint32_t*)(smx + SMO_LIST);
    int* scnt = (int*)(smx + SMO_CNT);
    int* sbase = (int*)(smx + SMO_BASE);
    uint32_t sb = smem_u32(smx);

    const uint32_t* gB = g_ebf + (size_t)n * Mm * 32;
    #pragma unroll
    for (int cc = 0; cc < 2; cc++) {
        #pragma unroll
        for (int i = 0; i < 4; i++) {
            int idx16 = t + i * 256;
            int row = idx16 >> 3, c16 = idx16 & 7;
            CP_ASYNC16(sb + SMO_B + (uint32_t)(cc * 16384) +
                       SWZ((uint32_t)(row * 128 + c16 * 16)),
                       gB + (cc * 128 + row) * 32 + c16 * 4);
        }
        CP_COMMIT();
    }
    #pragma unroll
    for (int i = 0; i < 4; i++) ens[t + i * 256] = g_enorm[n * Mm + t + i * 256];
    if (t < 128) xn[t] = g_xnorm[(size_t)n * BL + kbase + t];
    if (t == 0) *scnt = 0;
    {
        const uint32_t* gA = g_xbf + ((size_t)n * BL + kbase) * 32;
        #pragma unroll
        for (int i = 0; i < 16; i++) {
            int idx = t + i * 256;
            int row = idx >> 5, c4 = idx & 31;
            *(uint32_t*)(smx + SMO_A + SWZ((uint32_t)(row * 128 + c4 * 4))) = gA[idx];
        }
    }
    __syncthreads();

    uint32_t af[4][4];
    const int r0 = w * 16;
    #pragma unroll
    for (int s = 0; s < 4; s++) {
        uint32_t addr = sb + SMO_A +
            SWZ((uint32_t)((r0 + (lane & 15)) * 128 + (2 * s + (lane >> 4)) * 16));
        LDSM4(af[s][0], af[s][1], af[s][2], af[s][3], addr);
    }
    float Sx1 = xn[r0 + g], Sx2 = xn[r0 + 8 + g];
    float emax = sqrtf(__int_as_float(g_emaxbits[n]));
    const int row1 = n * BL + kbase + r0 + g;
    const int row2 = row1 + 8;

    // per-thread swizzled LDSM base offsets (swizzle invariant to +1024 steps)
    const uint32_t a1b = SWZ((uint32_t)((lane & 7) * 128 + (lane >> 3) * 16));
    const uint32_t a2b = SWZ((uint32_t)((lane & 7) * 128 + (4 + (lane >> 3)) * 16));

    float vmin0 = 3.4e38f, vmin1 = 3.4e38f;
    float thr0 = 0.f, thr1 = 0.f;

    for (int c = 0; c < 16; c++) {
        if (c < 14) { CP_WAIT(1); } else { CP_WAIT(0); }
        __syncthreads();
        uint32_t ub = sb + SMO_B + (uint32_t)((c & 1) * 16384);
        int nbase = (c & 7) * 128;

        uint32_t bf0[8], bf1[8];
        LDSM4(bf0[0], bf0[1], bf0[2], bf0[3], ub + a1b);
        LDSM4(bf0[4], bf0[5], bf0[6], bf0[7], ub + a2b);

        if (c < 8) {
            #pragma unroll
            for (int mc = 0; mc < 16; mc += 2) {
                // prefetch mc+1 while computing mc
                LDSM4(bf1[0], bf1[1], bf1[2], bf1[3], ub + a1b + (mc + 1) * 1024);
                LDSM4(bf1[4], bf1[5], bf1[6], bf1[7], ub + a2b + (mc + 1) * 1024);
                {
                    float acc[4]; do_mma(acc, af, bf0);
                    float2 en2 = *(float2*)&ens[nbase + mc * 8 + q * 2];
                    vmin0 = fminf(vmin0, __fmaf_rn(-2.f, acc[0], en2.x));
                    vmin0 = fminf(vmin0, __fmaf_rn(-2.f, acc[1], en2.y));
                    vmin1 = fminf(vmin1, __fmaf_rn(-2.f, acc[2], en2.x));
                    vmin1 = fminf(vmin1, __fmaf_rn(-2.f, acc[3], en2.y));
                }
                if (mc + 2 < 16) {
                    LDSM4(bf0[0], bf0[1], bf0[2], bf0[3], ub + a1b + (mc + 2) * 1024);
                    LDSM4(bf0[4], bf0[5], bf0[6], bf0[7], ub + a2b + (mc + 2) * 1024);
                }
                {
                    float acc[4]; do_mma(acc, af, bf1);
                    float2 en2 = *(float2*)&ens[nbase + (mc + 1) * 8 + q * 2];
                    vmin0 = fminf(vmin0, __fmaf_rn(-2.f, acc[0], en2.x));
                    vmin0 = fminf(vmin0, __fmaf_rn(-2.f, acc[1], en2.y));
                    vmin1 = fminf(vmin1, __fmaf_rn(-2.f, acc[2], en2.x));
                    vmin1 = fminf(vmin1, __fmaf_rn(-2.f, acc[3], en2.y));
                }
            }
            if (c == 7) {
                vmin0 = fminf(vmin0, __shfl_xor_sync(0xffffffffu, vmin0, 1));
                vmin0 = fminf(vmin0, __shfl_xor_sync(0xffffffffu, vmin0, 2));
                vmin1 = fminf(vmin1, __shfl_xor_sync(0xffffffffu, vmin1, 1));
                vmin1 = fminf(vmin1, __shfl_xor_sync(0xffffffffu, vmin1, 2));
                thr0 = vmin0 + 0.04f * sqrtf(Sx1) * emax + 1e-4f;
                thr1 = vmin1 + 0.04f * sqrtf(Sx2) * emax + 1e-4f;
            }
        } else {
            #pragma unroll
            for (int mc = 0; mc < 16; mc += 2) {
                LDSM4(bf1[0], bf1[1], bf1[2], bf1[3], ub + a1b + (mc + 1) * 1024);
                LDSM4(bf1[4], bf1[5], bf1[6], bf1[7], ub + a2b + (mc + 1) * 1024);
                #pragma unroll
                for (int hh = 0; hh < 2; hh++) {
                    const uint32_t* bfc = hh ? bf1 : bf0;
                    int mcc = mc + hh;
                    if (hh == 1 && mc + 2 < 16) {
                        LDSM4(bf0[0], bf0[1], bf0[2], bf0[3], ub + a1b + (mc + 2) * 1024);
                        LDSM4(bf0[4], bf0[5], bf0[6], bf0[7], ub + a2b + (mc + 2) * 1024);
                    }
                    float acc[4]; do_mma(acc, af, bfc);
                    int m0 = nbase + mcc * 8 + q * 2;
                    float2 en2 = *(float2*)&ens[m0];
                    float s0 = __fmaf_rn(-2.f, acc[0], en2.x);
                    float s1 = __fmaf_rn(-2.f, acc[1], en2.y);
                    float s2 = __fmaf_rn(-2.f, acc[2], en2.x);
                    float s3 = __fmaf_rn(-2.f, acc[3], en2.y);
                    if (s0 <= thr0 || s1 <= thr0 || s2 <= thr1 || s3 <= thr1) {
                        #pragma unroll
                        for (int e = 0; e < 4; e++) {
                            float sv = e == 0 ? s0 : (e == 1 ? s1 : (e == 2 ? s2 : s3));
                            float th = (e < 2) ? thr0 : thr1;
                            if (sv <= th) {
                                uint32_t rowg = (uint32_t)((e < 2) ? row1 : row2);
                                uint32_t v = (rowg << 10) | (uint32_t)(m0 + (e & 1));
                                int ix = atomicAdd(scnt, 1);
                                if (ix < LCAP) slist[ix] = v;
                                else { int gi = atomicAdd(&g_nc, 1); g_cand[gi] = v; }
                            }
                        }
                    }
                }
            }
        }

        __syncthreads();
        if (c <= 13) {
            int nc = (c + 2) & 7;
            const uint32_t* gc = gB + (size_t)nc * 128 * 32;
            uint32_t db = sb + SMO_B + (uint32_t)((c & 1) * 16384);
            #pragma unroll
            for (int i = 0; i < 4; i++) {
                int idx16 = t + i * 256;
                int row = idx16 >> 3, c16 = idx16 & 7;
                CP_ASYNC16(db + SWZ((uint32_t)(row * 128 + c16 * 16)),
                           gc + row * 32 + c16 * 4);
            }
            CP_COMMIT();
        }
    }

    __syncthreads();
    int cnt = *scnt; if (cnt > LCAP) cnt = LCAP;
    if (t == 0) *sbase = atomicAdd(&g_nc, cnt);
    __syncthreads();
    int base = *sbase;
    for (int i = t; i < cnt; i += 256) g_cand[base + i] = slist[i];
}

// ---------------------------------------------------------------------------
// Exact rescore: reference-bit fp32 serial chain, atomicMin on sortable key64.
__global__ void k_rescore(const float* __restrict__ emb) {
    int total = g_nc;
    for (int i = blockIdx.x * 256 + threadIdx.x; i < total; i += 262144) {
        uint32_t v = g_cand[i];
        int rowg = v >> 10, m = v & 1023;
        int n = rowg >> 16;
        float Sx = g_xnorm[rowg];
        float en = g_enorm[n * Mm + m];
        const float* xr = g_xt + (size_t)rowg * 64;
        const float* er = emb + ((size_t)n * Mm + m) * 64;
        float dot = 0.f;
        #pragma unroll 16
        for (int d = 0; d < 64; d++) dot = __fmaf_rn(xr[d], er[d], dot);
        float sc = __fadd_rn(__fadd_rn(Sx, en), __fmul_rn(-2.f, dot));
        uint32_t fb = __float_as_uint(sc);
        fb ^= ((uint32_t)((int32_t)fb >> 31)) | 0x80000000u;
        unsigned long long key = ((unsigned long long)fb << 32) | (uint32_t)m;
        atomicMin(&g_key[rowg], key);
    }
}

// ---------------------------------------------------------------------------
// Fused extract + dw scatter. One warp per row.
__global__ void k_dw(float* __restrict__ out) {
    int gw = (blockIdx.x * blockDim.x + threadIdx.x) >> 5;
    int lane = threadIdx.x & 31;
    if (gw >= Nn * BL) return;
    int n = gw >> 16, k = gw & 65535;
    int m = 0;
    if (lane == 0) {
        m = (int)(uint32_t)g_key[gw];
        g_idx[gw] = m;
        atomicAdd(&g_cnt[n * Mm + m], 1);
        out[OFF_IDX + ((long long)(k >> 4) * Nn + n) * Ll + (k & 15)] = (float)m;
    }
    m = __shfl_sync(0xffffffffu, m, 0);
    const float* xr = g_xt + (size_t)gw * 64;
    float* dwp = g_dw + ((size_t)n * Mm + m) * 64;
    atomicAdd(dwp + lane,      xr[lane]);
    atomicAdd(dwp + lane + 32, xr[lane + 32]);
}

// ---------------------------------------------------------------------------
__global__ void k_ema(const float* __restrict__ ema_count, float* __restrict__ out) {
    __shared__ float red[1024];
    int t = threadIdx.x;
    float perp = 0.0f;
    for (int n = 0; n < 4; n++) {
        float c = (float)g_cnt[n * Mm + t];
        float raw = DECAYF * ema_count[n * Mm + t] + (1.0f - DECAYF) * c;
        red[t] = raw; __syncthreads();
        for (int s = 512; s > 0; s >>= 1) { if (t < s) red[t] += red[t + s]; __syncthreads(); }
        float nsum = red[0]; __syncthreads();
        float fin = (raw + EPSF) / (nsum + Mm * EPSF) * nsum;
        out[OFF_CNT + n * Mm + t] = fin;
        g_fcnt[n * Mm + t] = fin;
        float avg = c * (1.0f / 65536.0f);
        float term = avg * logf(avg + 1e-10f);
        red[t] = term; __syncthreads();
        for (int s = 512; s > 0; s >>= 1) { if (t < s) red[t] += red[t + s]; __syncthreads(); }
        if (t == 0) perp += expf(-red[0]);
        __syncthreads();
    }
    if (t == 0) out[OFF_PERP] = perp;
}

// ---------------------------------------------------------------------------
__global__ void k_weight(const float* __restrict__ ema_weight, float* __restrict__ out) {
    int i = blockIdx.x * 256 + threadIdx.x;
    float w = DECAYF * ema_weight[i] + (1.0f - DECAYF) * g_dw[i];
    out[OFF_EMW + i] = w;
    out[OFF_EMB + i] = w / g_fcnt[i >> 6];
}

// ---------------------------------------------------------------------------
__global__ void k_gather(const float* __restrict__ x, const float* __restrict__ emb,
                         float* __restrict__ out) {
    __shared__ float se[16][68];
    __shared__ float red[256];
    int bn = blockIdx.x;
    int b = bn >> 2, n = bn & 3;
    int t = threadIdx.x;
    int r = t >> 4, c = t & 15;
    int idx = g_idx[n * BL + b * 16 + r];
    const float4* ep = (const float4*)emb + ((size_t)n * Mm + idx) * 16;
    float4 v = ep[c];
    se[r][c * 4] = v.x; se[r][c * 4 + 1] = v.y; se[r][c * 4 + 2] = v.z; se[r][c * 4 + 3] = v.w;
    __syncthreads();
    long long base = (long long)b * 4096 + n * 1024;
    float4 xv = ((const float4*)(x + base))[t];
    int lin = t * 4;
    int d = lin >> 4, l0 = lin & 15;
    float q0 = se[l0 + 0][d], q1 = se[l0 + 1][d], q2 = se[l0 + 2][d], q3 = se[l0 + 3][d];
    ((float4*)(out + OFF_ZQ + base))[t] = make_float4(q0, q1, q2, q3);
    float2* ez = (float2*)(out + OFF_EZQ + base);
    ez[2 * t]     = make_float2(q0, q1);
    ez[2 * t + 1] = make_float2(q2, q3);
    float d0 = xv.x - q0, d1 = xv.y - q1, d2 = xv.z - q2, d3 = xv.w - q3;
    red[t] = d0 * d0 + d1 * d1 + d2 * d2 + d3 * d3;
    __syncthreads();
    for (int s = 128; s > 0; s >>= 1) { if (t < s) red[t] += red[t + s]; __syncthreads(); }
    if (t == 0) g_losspart[bn] = red[0];
}

// ---------------------------------------------------------------------------
__global__ void k_loss(float* __restrict__ out) {
    __shared__ float red[1024];
    int t = threadIdx.x;
    float s = 0.0f;
    for (int i = t; i < Bb * Nn; i += 1024) s += g_losspart[i];
    red[t] = s; __syncthreads();
    for (int st = 512; st > 0; st >>= 1) { if (t < st) red[t] += red[t + st]; __syncthreads(); }
    if (t == 0) out[OFF_LOSS] = COMMITF * red[0] / 16777216.0f;
}

// ---------------------------------------------------------------------------
extern "C" void kernel_launch(void* const* d_in, const int* in_sizes, int n_in,
                              void* d_out, int out_size) {
    const float* x          = (const float*)d_in[0];
    const float* emb        = (const float*)d_in[1];
    const float* ema_count  = (const float*)d_in[2];
    const float* ema_weight = (const float*)d_in[3];
    float* out = (float*)d_out;

    cudaFuncSetAttribute(k_argmin, cudaFuncAttributeMaxDynamicSharedMemorySize, SM_BYTES);

    k_zero<<<1024, 256>>>();
    k_transpose<<<Bb * Nn, 256>>>(x);
    k_enorm<<<16, 256>>>(emb);
    dim3 ga(BL / 128, Nn);
    k_argmin<<<ga, 256, SM_BYTES>>>(out);
    k_rescore<<<1024, 256>>>(emb);
    k_dw<<<(Nn * BL) / 8, 256>>>(out);
    k_ema<<<1, 1024>>>(ema_count, out);
    k_weight<<<1024, 256>>>(ema_weight, out);
    k_gather<<<Bb * Nn, 256>>>(x, emb, out);
    k_loss<<<1, 1024>>>(out);
}

// round 16
// speedup vs baseline: 1.4069x; 1.4069x over previous
#include <cuda_runtime.h>
#include <cuda_bf16.h>
#include <cstdint>

#define Nn 4
#define Mm 1024
#define Dd 64
#define Ll 16
#define Bb 4096
#define BL 65536
#define DECAYF 0.999f
#define EPSF 1e-5f
#define COMMITF 0.05f

#define OFF_ZQ   0LL
#define OFF_LOSS 16777216LL
#define OFF_PERP 16777217LL
#define OFF_IDX  16777218LL
#define OFF_EZQ  17039362LL
#define OFF_EMB  33816578LL
#define OFF_CNT  34078722LL
#define OFF_EMW  34082818LL

__device__ float    g_xt[Nn * BL * Dd];
__device__ uint32_t g_xbf[Nn * BL * 32];    // x bf16 pairs, 128B/row
__device__ uint32_t g_ebf[Nn * Mm * 32];    // emb bf16 pairs, 128B/row
__device__ float    g_xnorm[Nn * BL];
__device__ int      g_idx[Nn * BL];
__device__ float    g_dw[Nn * Mm * Dd];
__device__ int      g_cnt[Nn * Mm];
__device__ float    g_enorm[Nn * Mm];
__device__ int      g_emaxbits[Nn];
__device__ float    g_fcnt[Nn * Mm];
__device__ float    g_losspart[Bb * Nn];
__device__ unsigned long long g_key[Nn * BL];   // per-row argmin key
__device__ uint32_t g_cand[2097152];            // candidate list
__device__ int      g_nc;
__device__ float    g_perp;

#define SWZ(off) ((off) ^ (((off) >> 3) & 0x70))
#define CP_ASYNC16(dst, src) \
    asm volatile("cp.async.cg.shared.global [%0], [%1], 16;" :: "r"(dst), "l"(src))
#define CP_COMMIT() asm volatile("cp.async.commit_group;" ::: "memory")
#define CP_WAIT(nconst) asm volatile("cp.async.wait_group %0;" :: "n"(nconst) : "memory")
#define LDSM4(r0, r1, r2, r3, addr) \
    asm volatile("ldmatrix.sync.aligned.m8n8.x4.shared.b16 {%0,%1,%2,%3}, [%4];" \
                 : "=r"(r0), "=r"(r1), "=r"(r2), "=r"(r3) : "r"(addr))

__device__ __forceinline__ uint32_t smem_u32(const void* p) {
    uint32_t a;
    asm("{ .reg .u64 t; cvta.to.shared.u64 t, %1; cvt.u32.u64 %0, t; }" : "=r"(a) : "l"(p));
    return a;
}
__device__ __forceinline__ void mma16816(float* d, const uint32_t* a, const uint32_t* b) {
    asm volatile("mma.sync.aligned.m16n8k16.row.col.f32.bf16.bf16.f32 "
                 "{%0,%1,%2,%3}, {%4,%5,%6,%7}, {%8,%9}, {%0,%1,%2,%3};"
                 : "+f"(d[0]), "+f"(d[1]), "+f"(d[2]), "+f"(d[3])
                 : "r"(a[0]), "r"(a[1]), "r"(a[2]), "r"(a[3]), "r"(b[0]), "r"(b[1]));
}

// ---------------------------------------------------------------------------
__global__ void k_zero() {
    int i = blockIdx.x * 256 + threadIdx.x;          // 262144 threads
    if (i < Nn * Mm * Dd) g_dw[i] = 0.0f;
    if (i < Nn * Mm)      g_cnt[i] = 0;
    if (i < Nn)           g_emaxbits[i] = 0;
    g_key[i] = 0xFFFFFFFFFFFFFFFFULL;
    if (i == 0) { g_nc = 0; g_perp = 0.0f; }
}

// ---------------------------------------------------------------------------
__global__ void k_transpose(const float* __restrict__ x) {
    __shared__ float s[16][65];
    int bn = blockIdx.x;
    int b = bn >> 2, n = bn & 3;
    int t = threadIdx.x;
    const float4* xp = (const float4*)(x + (long long)b * 4096 + n * 1024);
    float4 v = xp[t];
    int d = t >> 2, lb = (t & 3) * 4;
    s[lb + 0][d] = v.x; s[lb + 1][d] = v.y; s[lb + 2][d] = v.z; s[lb + 3][d] = v.w;
    __syncthreads();
    int r = t >> 4, c = t & 15;
    float4 w = make_float4(s[r][c * 4], s[r][c * 4 + 1], s[r][c * 4 + 2], s[r][c * 4 + 3]);
    size_t row = (size_t)n * BL + b * 16 + r;
    ((float4*)g_xt)[row * 16 + c] = w;
    g_xbf[row * 32 + c * 2] =
        (uint32_t)__bfloat16_as_ushort(__float2bfloat16_rn(w.x)) |
        ((uint32_t)__bfloat16_as_ushort(__float2bfloat16_rn(w.y)) << 16);
    g_xbf[row * 32 + c * 2 + 1] =
        (uint32_t)__bfloat16_as_ushort(__float2bfloat16_rn(w.z)) |
        ((uint32_t)__bfloat16_as_ushort(__float2bfloat16_rn(w.w)) << 16);
    if (t < 16) {
        float acc = 0.0f;
        #pragma unroll 8
        for (int dd = 0; dd < 64; dd++) {
            float vv = s[t][dd];
            acc = __fadd_rn(acc, __fmul_rn(vv, vv));
        }
        g_xnorm[(size_t)n * BL + b * 16 + t] = acc;
    }
}

// ---------------------------------------------------------------------------
__global__ void k_enorm(const float* __restrict__ emb) {
    int i = blockIdx.x * blockDim.x + threadIdx.x;   // 0..4095
    const float* e = emb + (size_t)i * 64;
    float s = 0.0f;
    #pragma unroll 8
    for (int d2 = 0; d2 < 32; d2++) {
        float v0 = e[2 * d2], v1 = e[2 * d2 + 1];
        s = __fadd_rn(s, __fmul_rn(v0, v0));
        s = __fadd_rn(s, __fmul_rn(v1, v1));
        g_ebf[(size_t)i * 32 + d2] =
            (uint32_t)__bfloat16_as_ushort(__float2bfloat16_rn(v0)) |
            ((uint32_t)__bfloat16_as_ushort(__float2bfloat16_rn(v1)) << 16);
    }
    g_enorm[i] = s;
    atomicMax(&g_emaxbits[i >> 10], __float_as_int(s));
}

// ---------------------------------------------------------------------------
// Two-pass HMMA prune (R14-proven loop). 256 thr, 128 rows/CTA,
// 8 chunks x 128 codes, dbl-buf. Pass 1: branchless approx min. Pass 2:
// push candidates (s <= certified thr) to per-CTA smem list.
#define SMO_ENS  0               // 4096B
#define SMO_XN   4096            // 512B
#define SMO_A    4608            // 16384B -> 20992
#define SMO_B    20992           // 2 x 16384 -> 53760
#define SMO_LIST 53760           // 1024 u32 -> 57856
#define SMO_CNT  57856
#define SMO_BASE 57860
#define SM_BYTES 57984
#define LCAP 1024

extern __shared__ char smx[];
__global__ void __launch_bounds__(256, 3)
k_argmin(float* __restrict__ out) {
    const int n = blockIdx.y;
    const int kbase = blockIdx.x * 128;
    const int t = threadIdx.x;
    const int lane = t & 31, w = t >> 5;
    const int g = lane >> 2, q = lane & 3;
    float* ens = (float*)(smx + SMO_ENS);
    float* xn  = (float*)(smx + SMO_XN);
    uint32_t* slist = (uint32_t*)(smx + SMO_LIST);
    int* scnt = (int*)(smx + SMO_CNT);
    int* sbase = (int*)(smx + SMO_BASE);
    uint32_t sb = smem_u32(smx);

    const uint32_t* gB = g_ebf + (size_t)n * Mm * 32;
    #pragma unroll
    for (int cc = 0; cc < 2; cc++) {
        #pragma unroll
        for (int i = 0; i < 4; i++) {
            int idx16 = t + i * 256;
            int row = idx16 >> 3, c16 = idx16 & 7;
            CP_ASYNC16(sb + SMO_B + (uint32_t)(cc * 16384) +
                       SWZ((uint32_t)(row * 128 + c16 * 16)),
                       gB + (cc * 128 + row) * 32 + c16 * 4);
        }
        CP_COMMIT();
    }
    #pragma unroll
    for (int i = 0; i < 4; i++) ens[t + i * 256] = g_enorm[n * Mm + t + i * 256];
    if (t < 128) xn[t] = g_xnorm[(size_t)n * BL + kbase + t];
    if (t == 0) *scnt = 0;
    {
        const uint32_t* gA = g_xbf + ((size_t)n * BL + kbase) * 32;
        #pragma unroll
        for (int i = 0; i < 16; i++) {
            int idx = t + i * 256;
            int row = idx >> 5, c4 = idx & 31;
            *(uint32_t*)(smx + SMO_A + SWZ((uint32_t)(row * 128 + c4 * 4))) = gA[idx];
        }
    }
    __syncthreads();

    uint32_t af[4][4];
    const int r0 = w * 16;
    #pragma unroll
    for (int s = 0; s < 4; s++) {
        uint32_t addr = sb + SMO_A +
            SWZ((uint32_t)((r0 + (lane & 15)) * 128 + (2 * s + (lane >> 4)) * 16));
        LDSM4(af[s][0], af[s][1], af[s][2], af[s][3], addr);
    }
    float Sx1 = xn[r0 + g], Sx2 = xn[r0 + 8 + g];
    float emax = sqrtf(__int_as_float(g_emaxbits[n]));
    const int row1 = n * BL + kbase + r0 + g;
    const int row2 = row1 + 8;

    float vmin0 = 3.4e38f, vmin1 = 3.4e38f;
    float thr0 = 0.f, thr1 = 0.f;

    for (int c = 0; c < 16; c++) {
        if (c < 14) { CP_WAIT(1); } else { CP_WAIT(0); }
        __syncthreads();
        uint32_t ub = sb + SMO_B + (uint32_t)((c & 1) * 16384);
        int nbase = (c & 7) * 128;

        if (c < 8) {
            #pragma unroll 2
            for (int mc = 0; mc < 16; mc++) {
                uint32_t bf[8];
                uint32_t a1 = ub + SWZ((uint32_t)((mc * 8 + (lane & 7)) * 128 + (lane >> 3) * 16));
                LDSM4(bf[0], bf[1], bf[2], bf[3], a1);
                uint32_t a2 = ub + SWZ((uint32_t)((mc * 8 + (lane & 7)) * 128 + (4 + (lane >> 3)) * 16));
                LDSM4(bf[4], bf[5], bf[6], bf[7], a2);
                float acc[4] = {0.f, 0.f, 0.f, 0.f};
                mma16816(acc, af[0], bf + 0);
                mma16816(acc, af[1], bf + 2);
                mma16816(acc, af[2], bf + 4);
                mma16816(acc, af[3], bf + 6);
                float2 en2 = *(float2*)&ens[nbase + mc * 8 + q * 2];
                vmin0 = fminf(vmin0, __fmaf_rn(-2.f, acc[0], en2.x));
                vmin0 = fminf(vmin0, __fmaf_rn(-2.f, acc[1], en2.y));
                vmin1 = fminf(vmin1, __fmaf_rn(-2.f, acc[2], en2.x));
                vmin1 = fminf(vmin1, __fmaf_rn(-2.f, acc[3], en2.y));
            }
            if (c == 7) {   // pass boundary: certified thresholds
                vmin0 = fminf(vmin0, __shfl_xor_sync(0xffffffffu, vmin0, 1));
                vmin0 = fminf(vmin0, __shfl_xor_sync(0xffffffffu, vmin0, 2));
                vmin1 = fminf(vmin1, __shfl_xor_sync(0xffffffffu, vmin1, 1));
                vmin1 = fminf(vmin1, __shfl_xor_sync(0xffffffffu, vmin1, 2));
                thr0 = vmin0 + 0.04f * sqrtf(Sx1) * emax + 1e-4f;
                thr1 = vmin1 + 0.04f * sqrtf(Sx2) * emax + 1e-4f;
            }
        } else {
            #pragma unroll 2
            for (int mc = 0; mc < 16; mc++) {
                uint32_t bf[8];
                uint32_t a1 = ub + SWZ((uint32_t)((mc * 8 + (lane & 7)) * 128 + (lane >> 3) * 16));
                LDSM4(bf[0], bf[1], bf[2], bf[3], a1);
                uint32_t a2 = ub + SWZ((uint32_t)((mc * 8 + (lane & 7)) * 128 + (4 + (lane >> 3)) * 16));
                LDSM4(bf[4], bf[5], bf[6], bf[7], a2);
                float acc[4] = {0.f, 0.f, 0.f, 0.f};
                mma16816(acc, af[0], bf + 0);
                mma16816(acc, af[1], bf + 2);
                mma16816(acc, af[2], bf + 4);
                mma16816(acc, af[3], bf + 6);
                int m0 = nbase + mc * 8 + q * 2;
                float2 en2 = *(float2*)&ens[m0];
                float s0 = __fmaf_rn(-2.f, acc[0], en2.x);
                float s1 = __fmaf_rn(-2.f, acc[1], en2.y);
                float s2 = __fmaf_rn(-2.f, acc[2], en2.x);
                float s3 = __fmaf_rn(-2.f, acc[3], en2.y);
                if (s0 <= thr0 || s1 <= thr0 || s2 <= thr1 || s3 <= thr1) {
                    #pragma unroll
                    for (int e = 0; e < 4; e++) {
                        float sv = e == 0 ? s0 : (e == 1 ? s1 : (e == 2 ? s2 : s3));
                        float th = (e < 2) ? thr0 : thr1;
                        if (sv <= th) {
                            uint32_t rowg = (uint32_t)((e < 2) ? row1 : row2);
                            uint32_t v = (rowg << 10) | (uint32_t)(m0 + (e & 1));
                            int ix = atomicAdd(scnt, 1);
                            if (ix < LCAP) slist[ix] = v;
                            else { int gi = atomicAdd(&g_nc, 1); g_cand[gi] = v; }
                        }
                    }
                }
            }
        }

        __syncthreads();
        if (c <= 13) {
            int nc = (c + 2) & 7;
            const uint32_t* gc = gB + (size_t)nc * 128 * 32;
            uint32_t db = sb + SMO_B + (uint32_t)((c & 1) * 16384);
            #pragma unroll
            for (int i = 0; i < 4; i++) {
                int idx16 = t + i * 256;
                int row = idx16 >> 3, c16 = idx16 & 7;
                CP_ASYNC16(db + SWZ((uint32_t)(row * 128 + c16 * 16)),
                           gc + row * 32 + c16 * 4);
            }
            CP_COMMIT();
        }
    }

    __syncthreads();
    int cnt = *scnt; if (cnt > LCAP) cnt = LCAP;
    if (t == 0) *sbase = atomicAdd(&g_nc, cnt);
    __syncthreads();
    int base = *sbase;
    for (int i = t; i < cnt; i += 256) g_cand[base + i] = slist[i];
}

// ---------------------------------------------------------------------------
// Exact rescore: reference-bit fp32 serial chain (float4 loads, in-order fma),
// atomicMin on sortable key64 (min score, tie -> lowest m).
__global__ void k_rescore(const float* __restrict__ emb) {
    int total = g_nc;
    for (int i = blockIdx.x * 256 + threadIdx.x; i < total; i += 262144) {
        uint32_t v = g_cand[i];
        int rowg = v >> 10, m = v & 1023;
        int n = rowg >> 16;
        float Sx = g_xnorm[rowg];
        float en = g_enorm[n * Mm + m];
        const float4* xr = (const float4*)(g_xt + (size_t)rowg * 64);
        const float4* er = (const float4*)(emb + ((size_t)n * Mm + m) * 64);
        float dot = 0.f;
        #pragma unroll
        for (int d4 = 0; d4 < 16; d4++) {
            float4 xv = __ldg(&xr[d4]);
            float4 ev = __ldg(&er[d4]);
            dot = __fmaf_rn(xv.x, ev.x, dot);
            dot = __fmaf_rn(xv.y, ev.y, dot);
            dot = __fmaf_rn(xv.z, ev.z, dot);
            dot = __fmaf_rn(xv.w, ev.w, dot);
        }
        float sc = __fadd_rn(__fadd_rn(Sx, en), __fmul_rn(-2.f, dot));
        uint32_t fb = __float_as_uint(sc);
        fb ^= ((uint32_t)((int32_t)fb >> 31)) | 0x80000000u;
        unsigned long long key = ((unsigned long long)fb << 32) | (uint32_t)m;
        atomicMin(&g_key[rowg], key);
    }
}

// ---------------------------------------------------------------------------
// Fused extract + dw scatter. One warp per row.
__global__ void k_dw(float* __restrict__ out) {
    int gw = (blockIdx.x * blockDim.x + threadIdx.x) >> 5;
    int lane = threadIdx.x & 31;
    if (gw >= Nn * BL) return;
    int n = gw >> 16, k = gw & 65535;
    int m = 0;
    if (lane == 0) {
        m = (int)(uint32_t)g_key[gw];
        g_idx[gw] = m;
        atomicAdd(&g_cnt[n * Mm + m], 1);
        out[OFF_IDX + ((long long)(k >> 4) * Nn + n) * Ll + (k & 15)] = (float)m;
    }
    m = __shfl_sync(0xffffffffu, m, 0);
    const float* xr = g_xt + (size_t)gw * 64;
    float* dwp = g_dw + ((size_t)n * Mm + m) * 64;
    atomicAdd(dwp + lane,      xr[lane]);
    atomicAdd(dwp + lane + 32, xr[lane + 32]);
}

// ---------------------------------------------------------------------------
// EMA counts + smoothing + perplexity partial. grid = 4 (one block per n).
__global__ void k_ema(const float* __restrict__ ema_count, float* __restrict__ out) {
    __shared__ float red[1024];
    int n = blockIdx.x;
    int t = threadIdx.x;
    float c = (float)g_cnt[n * Mm + t];
    float raw = DECAYF * ema_count[n * Mm + t] + (1.0f - DECAYF) * c;
    red[t] = raw; __syncthreads();
    for (int s = 512; s > 0; s >>= 1) { if (t < s) red[t] += red[t + s]; __syncthreads(); }
    float nsum = red[0]; __syncthreads();
    float fin = (raw + EPSF) / (nsum + Mm * EPSF) * nsum;
    out[OFF_CNT + n * Mm + t] = fin;
    g_fcnt[n * Mm + t] = fin;
    float avg = c * (1.0f / 65536.0f);
    float term = avg * logf(avg + 1e-10f);
    red[t] = term; __syncthreads();
    for (int s = 512; s > 0; s >>= 1) { if (t < s) red[t] += red[t + s]; __syncthreads(); }
    if (t == 0) atomicAdd(&g_perp, expf(-red[0]));
}

// ---------------------------------------------------------------------------
__global__ void k_weight(const float* __restrict__ ema_weight, float* __restrict__ out) {
    int i = blockIdx.x * 256 + threadIdx.x;
    float w = DECAYF * ema_weight[i] + (1.0f - DECAYF) * g_dw[i];
    out[OFF_EMW + i] = w;
    out[OFF_EMB + i] = w / g_fcnt[i >> 6];
}

// ---------------------------------------------------------------------------
__global__ void k_gather(const float* __restrict__ x, const float* __restrict__ emb,
                         float* __restrict__ out) {
    __shared__ float se[16][68];
    __shared__ float red[256];
    int bn = blockIdx.x;
    int b = bn >> 2, n = bn & 3;
    int t = threadIdx.x;
    int r = t >> 4, c = t & 15;
    int idx = g_idx[n * BL + b * 16 + r];
    const float4* ep = (const float4*)emb + ((size_t)n * Mm + idx) * 16;
    float4 v = ep[c];
    se[r][c * 4] = v.x; se[r][c * 4 + 1] = v.y; se[r][c * 4 + 2] = v.z; se[r][c * 4 + 3] = v.w;
    __syncthreads();
    long long base = (long long)b * 4096 + n * 1024;
    float4 xv = ((const float4*)(x + base))[t];
    int lin = t * 4;
    int d = lin >> 4, l0 = lin & 15;
    float q0 = se[l0 + 0][d], q1 = se[l0 + 1][d], q2 = se[l0 + 2][d], q3 = se[l0 + 3][d];
    ((float4*)(out + OFF_ZQ + base))[t] = make_float4(q0, q1, q2, q3);
    float2* ez = (float2*)(out + OFF_EZQ + base);
    ez[2 * t]     = make_float2(q0, q1);
    ez[2 * t + 1] = make_float2(q2, q3);
    float d0 = xv.x - q0, d1 = xv.y - q1, d2 = xv.z - q2, d3 = xv.w - q3;
    red[t] = d0 * d0 + d1 * d1 + d2 * d2 + d3 * d3;
    __syncthreads();
    for (int s = 128; s > 0; s >>= 1) { if (t < s) red[t] += red[t + s]; __syncthreads(); }
    if (t == 0) g_losspart[bn] = red[0];
}

// ---------------------------------------------------------------------------
__global__ void k_loss(float* __restrict__ out) {
    __shared__ float red[1024];
    int t = threadIdx.x;
    float s = 0.0f;
    for (int i = t; i < Bb * Nn; i += 1024) s += g_losspart[i];
    red[t] = s; __syncthreads();
    for (int st = 512; st > 0; st >>= 1) { if (t < st) red[t] += red[t + st]; __syncthreads(); }
    if (t == 0) {
        out[OFF_LOSS] = COMMITF * red[0] / 16777216.0f;
        out[OFF_PERP] = g_perp;
    }
}

// ---------------------------------------------------------------------------
extern "C" void kernel_launch(void* const* d_in, const int* in_sizes, int n_in,
                              void* d_out, int out_size) {
    const float* x          = (const float*)d_in[0];
    const float* emb        = (const float*)d_in[1];
    const float* ema_count  = (const float*)d_in[2];
    const float* ema_weight = (const float*)d_in[3];
    float* out = (float*)d_out;

    cudaFuncSetAttribute(k_argmin, cudaFuncAttributeMaxDynamicSharedMemorySize, SM_BYTES);

    k_zero<<<1024, 256>>>();
    k_transpose<<<Bb * Nn, 256>>>(x);
    k_enorm<<<16, 256>>>(emb);
    dim3 ga(BL / 128, Nn);
    k_argmin<<<ga, 256, SM_BYTES>>>(out);
    k_rescore<<<1024, 256>>>(emb);
    k_dw<<<(Nn * BL) / 8, 256>>>(out);
    k_ema<<<4, 1024>>>(ema_count, out);
    k_weight<<<1024, 256>>>(ema_weight, out);
    k_gather<<<Bb * Nn, 256>>>(x, emb, out);
    k_loss<<<1, 1024>>>(out);
}